// round 1
// baseline (speedup 1.0000x reference)
#include <cuda_runtime.h>

#define BATCH 8
#define CH    32
#define HH    256
#define WW    256
#define HW    (HH*WW)
#define EPSV  1e-5f

// ---------------- scratch (device globals; no allocation) ----------------
__device__ float g_x1[(size_t)BATCH*CH*HW];    // conv1 output            (64 MB)
__device__ float g_cat[(size_t)BATCH*CH*HW];   // ch0=guided, ch1..31=x3  (64 MB)
__device__ float g_cspn[(size_t)BATCH*HW];     // conv2 output            ( 2 MB)
__device__ float g_gk[(size_t)BATCH*9*HW];     // guide kernel (9ch)      (18 MB)
__device__ float g_gk2[(size_t)BATCH*9*HW];    // encoder(guide kernel)   (18 MB)

// ---------------- conv1: (x+guide+depth) -> 5x5 conv -> BN -> ReLU -------
// tile 32x8 pixels, 32 couts; thread = 4 pixels x 8 couts
__global__ __launch_bounds__(256) void conv1_kernel(
    const float* __restrict__ x,  const float* __restrict__ gu,
    const float* __restrict__ dp, const float* __restrict__ w,
    const float* __restrict__ bg, const float* __restrict__ bb,
    const float* __restrict__ bm, const float* __restrict__ bv)
{
    __shared__ float s_in[12*40];
    __shared__ float s_w[800];
    const int tid = threadIdx.x;
    const int cg  = tid >> 6;            // 0..3 -> couts cg*8..cg*8+7
    const int p   = tid & 63;
    const int px  = (p & 7) << 2;        // 0..28
    const int py  = p >> 3;              // 0..7
    const int bx0 = blockIdx.x << 5;
    const int by0 = blockIdx.y << 3;
    const int b   = blockIdx.z;

    float acc[8][4];
#pragma unroll
    for (int c = 0; c < 8; c++)
#pragma unroll
        for (int i = 0; i < 4; i++) acc[c][i] = 0.f;

#pragma unroll 1
    for (int cin = 0; cin < 32; cin++) {
        const size_t base = ((size_t)(b*32 + cin))*HW;
        for (int i = tid; i < 12*36; i += 256) {
            int r = i / 36, c2 = i - r*36;
            int gy = by0 - 2 + r, gx = bx0 - 2 + c2;
            float v = 0.f;
            if ((unsigned)gy < (unsigned)HH && (unsigned)gx < (unsigned)WW) {
                size_t idx = base + (size_t)gy*WW + gx;
                v = x[idx] + gu[idx] + dp[idx];
            }
            s_in[r*40 + c2] = v;
        }
        for (int i = tid; i < 800; i += 256) {
            int co = i / 25, q = i - co*25;
            s_w[i] = w[co*800 + cin*25 + q];
        }
        __syncthreads();
#pragma unroll
        for (int ky = 0; ky < 5; ky++) {
            const float* row = &s_in[(py+ky)*40 + px];
            float4 a  = *(const float4*)row;
            float4 b4 = *(const float4*)(row + 4);
            float win[8] = {a.x,a.y,a.z,a.w,b4.x,b4.y,b4.z,b4.w};
#pragma unroll
            for (int c = 0; c < 8; c++) {
                const float* wr = &s_w[(cg*8+c)*25 + ky*5];
#pragma unroll
                for (int kx = 0; kx < 5; kx++) {
                    float wv = wr[kx];
                    acc[c][0] = fmaf(win[kx+0], wv, acc[c][0]);
                    acc[c][1] = fmaf(win[kx+1], wv, acc[c][1]);
                    acc[c][2] = fmaf(win[kx+2], wv, acc[c][2]);
                    acc[c][3] = fmaf(win[kx+3], wv, acc[c][3]);
                }
            }
        }
        __syncthreads();
    }
    const int oy = by0 + py, ox = bx0 + px;
#pragma unroll
    for (int c = 0; c < 8; c++) {
        int cc = cg*8 + c;
        float s    = bg[cc] * rsqrtf(bv[cc] + EPSV);
        float bias = bb[cc] - bm[cc]*s;
        float4 o;
        o.x = fmaxf(fmaf(acc[c][0], s, bias), 0.f);
        o.y = fmaxf(fmaf(acc[c][1], s, bias), 0.f);
        o.z = fmaxf(fmaf(acc[c][2], s, bias), 0.f);
        o.w = fmaxf(fmaf(acc[c][3], s, bias), 0.f);
        *(float4*)&g_x1[((size_t)(b*32+cc))*HW + (size_t)oy*WW + ox] = o;
    }
}

// ---------------- generic 3x3 conv (pad 1) -------------------------------
// tile 32 x TH, couts in G groups of 8; thread = 4 pixels x 8 couts.
// GEN mode fuses the abs-sum normalization + g_mid + 9ch concat.
template<int CIN, int G, int TH, bool HASBN, bool RELU, bool GEN>
__global__ void conv3x3_kernel(
    const float* __restrict__ in, const float* __restrict__ w,
    const float* __restrict__ bg, const float* __restrict__ bb,
    const float* __restrict__ bm, const float* __restrict__ bv,
    float* __restrict__ out, int nco, int onch, int coff)
{
    constexpr int NPIX = 8*TH;
    constexpr int NT   = NPIX*G;
    constexpr int NCOP = G*8;
    __shared__ float s_in[(TH+2)*40];
    __shared__ float s_w[NCOP*9];
    const int tid = threadIdx.x;
    const int cg  = tid / NPIX;
    const int p   = tid % NPIX;
    const int px  = (p & 7) << 2;
    const int py  = p >> 3;
    const int bx0 = blockIdx.x << 5;
    const int by0 = blockIdx.y * TH;
    const int b   = blockIdx.z;

    float acc[8][4];
#pragma unroll
    for (int c = 0; c < 8; c++)
#pragma unroll
        for (int i = 0; i < 4; i++) acc[c][i] = 0.f;

#pragma unroll 1
    for (int cin = 0; cin < CIN; cin++) {
        const float* ib = in + ((size_t)(b*CIN + cin))*HW;
        for (int i = tid; i < (TH+2)*34; i += NT) {
            int r = i / 34, c2 = i - r*34;
            int gy = by0 - 1 + r, gx = bx0 - 1 + c2;
            s_in[r*40 + c2] = ((unsigned)gy < 256u && (unsigned)gx < 256u)
                              ? ib[gy*WW + gx] : 0.f;
        }
        for (int i = tid; i < NCOP*9; i += NT) {
            int co = i / 9, q = i - co*9;
            s_w[i] = (co < nco) ? w[(co*CIN + cin)*9 + q] : 0.f;
        }
        __syncthreads();
#pragma unroll
        for (int ky = 0; ky < 3; ky++) {
            const float* row = &s_in[(py+ky)*40 + px];
            float4 a  = *(const float4*)row;
            float4 b4 = *(const float4*)(row + 4);
            float win[8] = {a.x,a.y,a.z,a.w,b4.x,b4.y,b4.z,b4.w};
#pragma unroll
            for (int c = 0; c < 8; c++) {
                const float* wr = &s_w[(cg*8+c)*9 + ky*3];
#pragma unroll
                for (int kx = 0; kx < 3; kx++) {
                    float wv = wr[kx];
                    acc[c][0] = fmaf(win[kx+0], wv, acc[c][0]);
                    acc[c][1] = fmaf(win[kx+1], wv, acc[c][1]);
                    acc[c][2] = fmaf(win[kx+2], wv, acc[c][2]);
                    acc[c][3] = fmaf(win[kx+3], wv, acc[c][3]);
                }
            }
        }
        __syncthreads();
    }
    const int oy = by0 + py, ox = bx0 + px;
    if (GEN) {
        // G==1, nco==8 : full 8-channel vector is thread-local
        float v[8][4];
#pragma unroll
        for (int c = 0; c < 8; c++) {
            float s = 1.f, bias = 0.f;
            if (HASBN) { s = bg[c]*rsqrtf(bv[c]+EPSV); bias = bb[c]-bm[c]*s; }
#pragma unroll
            for (int i = 0; i < 4; i++) v[c][i] = fmaf(acc[c][i], s, bias);
        }
        float gk[9][4];
#pragma unroll
        for (int i = 0; i < 4; i++) {
            float asum = 0.f;
#pragma unroll
            for (int c = 0; c < 8; c++) asum += fabsf(v[c][i]);
            float inv = 1.f / asum;
            float ssum = 0.f;
#pragma unroll
            for (int c = 0; c < 8; c++) {
                float t = v[c][i]*inv;
                ssum += t;
                gk[c < 4 ? c : c+1][i] = t;
            }
            gk[4][i] = 1.f - ssum;
        }
#pragma unroll
        for (int j = 0; j < 9; j++) {
            float4 o = make_float4(gk[j][0], gk[j][1], gk[j][2], gk[j][3]);
            *(float4*)&out[((size_t)(b*onch + j))*HW + (size_t)oy*WW + ox] = o;
        }
    } else {
#pragma unroll
        for (int c = 0; c < 8; c++) {
            int cc = cg*8 + c;
            if (cc < nco) {
                float s = 1.f, bias = 0.f;
                if (HASBN) { s = bg[cc]*rsqrtf(bv[cc]+EPSV); bias = bb[cc]-bm[cc]*s; }
                float4 o;
                o.x = fmaf(acc[c][0], s, bias);
                o.y = fmaf(acc[c][1], s, bias);
                o.z = fmaf(acc[c][2], s, bias);
                o.w = fmaf(acc[c][3], s, bias);
                if (RELU) {
                    o.x = fmaxf(o.x, 0.f); o.y = fmaxf(o.y, 0.f);
                    o.z = fmaxf(o.z, 0.f); o.w = fmaxf(o.w, 0.f);
                }
                *(float4*)&out[((size_t)(b*onch + coff + cc))*HW + (size_t)oy*WW + ox] = o;
            }
        }
    }
}

// ---------------- conv2: 1x1 32->1 + BN + ReLU ---------------------------
__global__ __launch_bounds__(256) void conv2_kernel(
    const float* __restrict__ w2, const float* __restrict__ bg,
    const float* __restrict__ bb, const float* __restrict__ bm,
    const float* __restrict__ bv)
{
    __shared__ float sw[32];
    if (threadIdx.x < 32) sw[threadIdx.x] = w2[threadIdx.x];
    __syncthreads();
    int gid = blockIdx.x*256 + threadIdx.x;
    int b   = gid / (HW/4);
    int r4  = (gid - b*(HW/4))*4;
    const float* xb = g_x1 + (size_t)b*32*HW + r4;
    float4 acc = make_float4(0.f,0.f,0.f,0.f);
#pragma unroll 8
    for (int c = 0; c < 32; c++) {
        float4 vv = *(const float4*)(xb + (size_t)c*HW);
        float wv = sw[c];
        acc.x = fmaf(vv.x, wv, acc.x);
        acc.y = fmaf(vv.y, wv, acc.y);
        acc.z = fmaf(vv.z, wv, acc.z);
        acc.w = fmaf(vv.w, wv, acc.w);
    }
    float s    = bg[0]*rsqrtf(bv[0]+EPSV);
    float bias = bb[0] - bm[0]*s;
    float4 o;
    o.x = fmaxf(fmaf(acc.x, s, bias), 0.f);
    o.y = fmaxf(fmaf(acc.y, s, bias), 0.f);
    o.z = fmaxf(fmaf(acc.z, s, bias), 0.f);
    o.w = fmaxf(fmaf(acc.w, s, bias), 0.f);
    *(float4*)&g_cspn[(size_t)b*HW + r4] = o;
}

// ---------------- CSPN: 9-tap weighted sum -------------------------------
// (mid-patch substitution is a no-op: offset (0,0) patch == cspn_depth)
__global__ __launch_bounds__(256) void cspn_kernel()
{
    int gid = blockIdx.x*256 + threadIdx.x;
    int b   = gid / HW;
    int r   = gid - b*HW;
    int y   = r >> 8, x = r & 255;
    const float* cs = g_cspn + (size_t)b*HW;
    const float* k  = g_gk2 + (size_t)b*9*HW + r;
    float acc = 0.f;
#pragma unroll
    for (int j = 0; j < 9; j++) {
        int yy = y + j/3 - 1, xx = x + j%3 - 1;
        float pv = ((unsigned)yy < 256u && (unsigned)xx < 256u) ? cs[yy*WW+xx] : 0.f;
        acc = fmaf(pv, k[(size_t)j*HW], acc);
    }
    g_cat[(size_t)b*32*HW + r] = acc;   // channel 0
}

// ---------------- bilinear upsample 2x (align-corners style) -------------
__global__ __launch_bounds__(256) void upsample_kernel(float* __restrict__ out)
{
    int gid = blockIdx.x*256 + threadIdx.x;
    int xo  = (gid & 127) << 2;
    int t   = gid >> 7;
    int yo  = t & 511;
    int bc  = t >> 9;                          // b*32 + c
    const float* src = g_cat + (size_t)bc*HW;
    const float scale = 255.f/511.f;
    float ysf = yo * scale;
    int y0 = (int)ysf;
    float wy = ysf - (float)y0;
    int y1 = min(y0+1, 255);
    const float* r0 = src + y0*WW;
    const float* r1 = src + y1*WW;
    float res[4];
#pragma unroll
    for (int i = 0; i < 4; i++) {
        float xsf = (xo+i) * scale;
        int x0 = (int)xsf;
        float wx = xsf - (float)x0;
        int x1 = min(x0+1, 255);
        float top = r0[x0]*(1.f-wx) + r0[x1]*wx;
        float bot = r1[x0]*(1.f-wx) + r1[x1]*wx;
        res[i] = top*(1.f-wy) + bot*wy;
    }
    *(float4*)&out[((size_t)bc*512 + yo)*512 + xo] =
        make_float4(res[0], res[1], res[2], res[3]);
}

// --------------------------------------------------------------------------
extern "C" void kernel_launch(void* const* d_in, const int* in_sizes, int n_in,
                              void* d_out, int out_size)
{
    const float* x     = (const float*)d_in[0];
    const float* guide = (const float*)d_in[1];
    const float* depth = (const float*)d_in[2];
    const float* c1w   = (const float*)d_in[3];
    const float* b1g = (const float*)d_in[4],  *b1b = (const float*)d_in[5];
    const float* b1m = (const float*)d_in[6],  *b1v = (const float*)d_in[7];
    const float* c2w   = (const float*)d_in[8];
    const float* b2g = (const float*)d_in[9],  *b2b = (const float*)d_in[10];
    const float* b2m = (const float*)d_in[11], *b2v = (const float*)d_in[12];
    const float* c3w   = (const float*)d_in[13];
    const float* b3g = (const float*)d_in[14], *b3b = (const float*)d_in[15];
    const float* b3m = (const float*)d_in[16], *b3v = (const float*)d_in[17];
    const float* gw    = (const float*)d_in[18];
    const float* bgg = (const float*)d_in[19], *bgb = (const float*)d_in[20];
    const float* bgm = (const float*)d_in[21], *bgv = (const float*)d_in[22];
    const float* enc   = (const float*)d_in[23];

    float *px1, *pcat, *pgk, *pgk2;
    cudaGetSymbolAddress((void**)&px1,  g_x1);
    cudaGetSymbolAddress((void**)&pcat, g_cat);
    cudaGetSymbolAddress((void**)&pgk,  g_gk);
    cudaGetSymbolAddress((void**)&pgk2, g_gk2);

    dim3 gridA(WW/32, HH/8, BATCH);

    // 1) fused add + conv1 5x5 + BN + ReLU -> g_x1
    conv1_kernel<<<gridA, 256>>>(x, guide, depth, c1w, b1g, b1b, b1m, b1v);

    // 2) conv3 3x3 32->31 + BN + ReLU -> g_cat channels 1..31
    conv3x3_kernel<32,4,8,true,true,false><<<gridA, 256>>>(
        px1, c3w, b3g, b3b, b3m, b3v, pcat, 31, 32, 1);

    // 3) gen 3x3 32->8 + BN + normalize + concat(g_mid) -> g_gk (9 ch)
    dim3 gridG(WW/32, HH/16, BATCH);
    conv3x3_kernel<32,1,16,true,false,true><<<gridG, 128>>>(
        px1, gw, bgg, bgb, bgm, bgv, pgk, 8, 9, 0);

    // 4) conv2 1x1 32->1 + BN + ReLU -> g_cspn
    conv2_kernel<<<BATCH*HW/1024, 256>>>(c2w, b2g, b2b, b2m, b2v);

    // 5) encoder conv 9->9 3x3 (no BN) -> g_gk2
    conv3x3_kernel<9,2,8,false,false,false><<<gridA, 128>>>(
        pgk, enc, nullptr, nullptr, nullptr, nullptr, pgk2, 9, 9, 0);

    // 6) CSPN weighted sum -> g_cat channel 0
    cspn_kernel<<<BATCH*HW/256, 256>>>();

    // 7) bilinear upsample 2x -> d_out
    upsample_kernel<<<(BATCH*32*512*512)/1024, 256>>>((float*)d_out);
}

// round 2
// speedup vs baseline: 1.0551x; 1.0551x over previous
#include <cuda_runtime.h>

#define BATCH 8
#define CH    32
#define HH    256
#define WW    256
#define HW    (HH*WW)
#define EPSV  1e-5f

typedef unsigned long long ull;

// ---------------- packed f32x2 helpers -----------------------------------
__device__ __forceinline__ ull pk2(float lo, float hi) {
    ull r;
    asm("mov.b64 %0, {%1, %2};" : "=l"(r)
        : "r"(__float_as_uint(lo)), "r"(__float_as_uint(hi)));
    return r;
}
__device__ __forceinline__ void fma2(ull& d, ull a, ull b) {
    asm("fma.rn.f32x2 %0, %1, %2, %3;" : "=l"(d) : "l"(a), "l"(b), "l"(d));
}
__device__ __forceinline__ float2 upk(ull v) {
    unsigned lo, hi;
    asm("mov.b64 {%0, %1}, %2;" : "=r"(lo), "=r"(hi) : "l"(v));
    return make_float2(__uint_as_float(lo), __uint_as_float(hi));
}

// ---------------- scratch (device globals; no allocation) ----------------
__device__ float g_x1[(size_t)BATCH*CH*HW];    // conv1 output            (64 MB)
__device__ float g_cat[(size_t)BATCH*CH*HW];   // ch0=guided, ch1..31=x3  (64 MB)
__device__ float g_cspn[(size_t)BATCH*HW];     // conv2 output            ( 2 MB)
__device__ float g_gk[(size_t)BATCH*9*HW];     // guide kernel (9ch)      (18 MB)
__device__ float g_gk2[(size_t)BATCH*9*HW];    // encoder(guide kernel)   (18 MB)

// ---------------- conv1: (x+guide+depth) -> 5x5 conv -> BN -> ReLU -------
// tile 32x8 pixels, 32 couts; thread = 4 pixels x 8 couts (f32x2 packed)
__global__ __launch_bounds__(256) void conv1_kernel(
    const float* __restrict__ x,  const float* __restrict__ gu,
    const float* __restrict__ dp, const float* __restrict__ w,
    const float* __restrict__ bg, const float* __restrict__ bb,
    const float* __restrict__ bm, const float* __restrict__ bv)
{
    __shared__ float s_in[2][12*40];
    __shared__ ull   s_w2[2][800];
    const int tid = threadIdx.x;
    const int cg  = tid >> 6;            // 0..3 -> couts cg*8..cg*8+7
    const int p   = tid & 63;
    const int px  = (p & 7) << 2;        // 0..28
    const int py  = p >> 3;              // 0..7
    const int bx0 = blockIdx.x << 5;
    const int by0 = blockIdx.y << 3;
    const int b   = blockIdx.z;

    ull acc01[8], acc23[8];
#pragma unroll
    for (int c = 0; c < 8; c++) { acc01[c] = 0ULL; acc23[c] = 0ULL; }

    float rin[2];
    float rw[4];

    auto fetch = [&](int cin) {
#pragma unroll
        for (int t = 0; t < 2; t++) {
            int i = tid + t*256;
            float v = 0.f;
            if (i < 12*36) {
                int r = i / 36, c2 = i - r*36;
                int gy = by0 - 2 + r, gx = bx0 - 2 + c2;
                if ((unsigned)gy < 256u && (unsigned)gx < 256u) {
                    size_t idx = ((size_t)(b*32 + cin))*HW + (size_t)gy*WW + gx;
                    v = x[idx] + gu[idx] + dp[idx];
                }
            }
            rin[t] = v;
        }
#pragma unroll
        for (int t = 0; t < 4; t++) {
            int i = tid + t*256;
            if (i < 800) {
                int co = i / 25, q = i - co*25;
                rw[t] = w[co*800 + cin*25 + q];
            }
        }
    };
    auto commit = [&](int buf) {
#pragma unroll
        for (int t = 0; t < 2; t++) {
            int i = tid + t*256;
            if (i < 12*36) {
                int r = i / 36, c2 = i - r*36;
                s_in[buf][r*40 + c2] = rin[t];
            }
        }
#pragma unroll
        for (int t = 0; t < 4; t++) {
            int i = tid + t*256;
            if (i < 800) s_w2[buf][i] = pk2(rw[t], rw[t]);
        }
    };

    fetch(0); commit(0);

#pragma unroll 1
    for (int cin = 0; cin < 32; cin++) {
        __syncthreads();                        // buf(cin) ready
        if (cin + 1 < 32) fetch(cin + 1);
        const int buf = cin & 1;
#pragma unroll
        for (int ky = 0; ky < 5; ky++) {
            const float* row = &s_in[buf][(py+ky)*40 + px];
            float4 a  = *(const float4*)row;
            float4 b4 = *(const float4*)(row + 4);
            ull pe0 = pk2(a.x,  a.y),  pe1 = pk2(a.z,  a.w);
            ull pe2 = pk2(b4.x, b4.y), pe3 = pk2(b4.z, b4.w);
            ull po0 = pk2(a.y,  a.z),  po1 = pk2(a.w,  b4.x);
            ull po2 = pk2(b4.y, b4.z);
#pragma unroll
            for (int c = 0; c < 8; c++) {
                const ull* wr = &s_w2[buf][(cg*8+c)*25 + ky*5];
                ull w0 = wr[0], w1 = wr[1], w2 = wr[2], w3 = wr[3], w4 = wr[4];
                fma2(acc01[c], pe0, w0); fma2(acc23[c], pe1, w0);
                fma2(acc01[c], po0, w1); fma2(acc23[c], po1, w1);
                fma2(acc01[c], pe1, w2); fma2(acc23[c], pe2, w2);
                fma2(acc01[c], po1, w3); fma2(acc23[c], po2, w3);
                fma2(acc01[c], pe2, w4); fma2(acc23[c], pe3, w4);
            }
        }
        __syncthreads();                        // done reading buf(cin-1)'s twin
        if (cin + 1 < 32) commit((cin + 1) & 1);
    }

    const int oy = by0 + py, ox = bx0 + px;
#pragma unroll
    for (int c = 0; c < 8; c++) {
        int cc = cg*8 + c;
        float s    = bg[cc] * rsqrtf(bv[cc] + EPSV);
        float bias = bb[cc] - bm[cc]*s;
        float2 v01 = upk(acc01[c]), v23 = upk(acc23[c]);
        float4 o;
        o.x = fmaxf(fmaf(v01.x, s, bias), 0.f);
        o.y = fmaxf(fmaf(v01.y, s, bias), 0.f);
        o.z = fmaxf(fmaf(v23.x, s, bias), 0.f);
        o.w = fmaxf(fmaf(v23.y, s, bias), 0.f);
        *(float4*)&g_x1[((size_t)(b*32+cc))*HW + (size_t)oy*WW + ox] = o;
    }
}

// ---------------- generic 3x3 conv (pad 1), f32x2 packed -----------------
// tile 32 x TH, couts in G groups of 8; thread = 4 pixels x 8 couts.
// GEN mode fuses the abs-sum normalization + g_mid + 9ch concat.
template<int CIN, int G, int TH, bool HASBN, bool RELU, bool GEN>
__global__ void conv3x3_kernel(
    const float* __restrict__ in, const float* __restrict__ w,
    const float* __restrict__ bg, const float* __restrict__ bb,
    const float* __restrict__ bm, const float* __restrict__ bv,
    float* __restrict__ out, int nco, int onch, int coff)
{
    constexpr int NPIX = 8*TH;
    constexpr int NT   = NPIX*G;
    constexpr int NCOP = G*8;
    constexpr int IN_ELEMS = (TH+2)*34;
    constexpr int IN_IT = (IN_ELEMS + NT - 1) / NT;
    constexpr int W_ELEMS = NCOP*9;
    constexpr int W_IT = (W_ELEMS + NT - 1) / NT;

    __shared__ float s_in[2][(TH+2)*40];
    __shared__ ull   s_w2[2][NCOP*9];
    const int tid = threadIdx.x;
    const int cg  = tid / NPIX;
    const int p   = tid % NPIX;
    const int px  = (p & 7) << 2;
    const int py  = p >> 3;
    const int bx0 = blockIdx.x << 5;
    const int by0 = blockIdx.y * TH;
    const int b   = blockIdx.z;

    ull acc01[8], acc23[8];
#pragma unroll
    for (int c = 0; c < 8; c++) { acc01[c] = 0ULL; acc23[c] = 0ULL; }

    float rin[IN_IT];
    float rw[W_IT];

    auto fetch = [&](int cin) {
        const float* ib = in + ((size_t)(b*CIN + cin))*HW;
#pragma unroll
        for (int t = 0; t < IN_IT; t++) {
            int i = tid + t*NT;
            float v = 0.f;
            if (i < IN_ELEMS) {
                int r = i / 34, c2 = i - r*34;
                int gy = by0 - 1 + r, gx = bx0 - 1 + c2;
                if ((unsigned)gy < 256u && (unsigned)gx < 256u)
                    v = ib[gy*WW + gx];
            }
            rin[t] = v;
        }
#pragma unroll
        for (int t = 0; t < W_IT; t++) {
            int i = tid + t*NT;
            float v = 0.f;
            if (i < W_ELEMS) {
                int co = i / 9, q = i - co*9;
                if (co < nco) v = w[(co*CIN + cin)*9 + q];
            }
            rw[t] = v;
        }
    };
    auto commit = [&](int buf) {
#pragma unroll
        for (int t = 0; t < IN_IT; t++) {
            int i = tid + t*NT;
            if (i < IN_ELEMS) {
                int r = i / 34, c2 = i - r*34;
                s_in[buf][r*40 + c2] = rin[t];
            }
        }
#pragma unroll
        for (int t = 0; t < W_IT; t++) {
            int i = tid + t*NT;
            if (i < W_ELEMS) s_w2[buf][i] = pk2(rw[t], rw[t]);
        }
    };

    fetch(0); commit(0);

#pragma unroll 1
    for (int cin = 0; cin < CIN; cin++) {
        __syncthreads();
        if (cin + 1 < CIN) fetch(cin + 1);
        const int buf = cin & 1;
#pragma unroll
        for (int ky = 0; ky < 3; ky++) {
            const float* row = &s_in[buf][(py+ky)*40 + px];
            float4 a  = *(const float4*)row;
            float2 b2 = *(const float2*)(row + 4);
            ull pe0 = pk2(a.x, a.y), pe1 = pk2(a.z, a.w), pe2 = pk2(b2.x, b2.y);
            ull po0 = pk2(a.y, a.z), po1 = pk2(a.w, b2.x);
#pragma unroll
            for (int c = 0; c < 8; c++) {
                const ull* wr = &s_w2[buf][(cg*8+c)*9 + ky*3];
                ull w0 = wr[0], w1 = wr[1], w2 = wr[2];
                fma2(acc01[c], pe0, w0); fma2(acc23[c], pe1, w0);
                fma2(acc01[c], po0, w1); fma2(acc23[c], po1, w1);
                fma2(acc01[c], pe1, w2); fma2(acc23[c], pe2, w2);
            }
        }
        __syncthreads();
        if (cin + 1 < CIN) commit((cin + 1) & 1);
    }

    const int oy = by0 + py, ox = bx0 + px;
    if (GEN) {
        // G==1, nco==8 : full 8-channel vector is thread-local
        float v[8][4];
#pragma unroll
        for (int c = 0; c < 8; c++) {
            float s = 1.f, bias = 0.f;
            if (HASBN) { s = bg[c]*rsqrtf(bv[c]+EPSV); bias = bb[c]-bm[c]*s; }
            float2 v01 = upk(acc01[c]), v23 = upk(acc23[c]);
            v[c][0] = fmaf(v01.x, s, bias);
            v[c][1] = fmaf(v01.y, s, bias);
            v[c][2] = fmaf(v23.x, s, bias);
            v[c][3] = fmaf(v23.y, s, bias);
        }
        float gk[9][4];
#pragma unroll
        for (int i = 0; i < 4; i++) {
            float asum = 0.f;
#pragma unroll
            for (int c = 0; c < 8; c++) asum += fabsf(v[c][i]);
            float inv = 1.f / asum;
            float ssum = 0.f;
#pragma unroll
            for (int c = 0; c < 8; c++) {
                float t = v[c][i]*inv;
                ssum += t;
                gk[c < 4 ? c : c+1][i] = t;
            }
            gk[4][i] = 1.f - ssum;
        }
#pragma unroll
        for (int j = 0; j < 9; j++) {
            float4 o = make_float4(gk[j][0], gk[j][1], gk[j][2], gk[j][3]);
            *(float4*)&out[((size_t)(b*onch + j))*HW + (size_t)oy*WW + ox] = o;
        }
    } else {
#pragma unroll
        for (int c = 0; c < 8; c++) {
            int cc = cg*8 + c;
            if (cc < nco) {
                float s = 1.f, bias = 0.f;
                if (HASBN) { s = bg[cc]*rsqrtf(bv[cc]+EPSV); bias = bb[cc]-bm[cc]*s; }
                float2 v01 = upk(acc01[c]), v23 = upk(acc23[c]);
                float4 o;
                o.x = fmaf(v01.x, s, bias);
                o.y = fmaf(v01.y, s, bias);
                o.z = fmaf(v23.x, s, bias);
                o.w = fmaf(v23.y, s, bias);
                if (RELU) {
                    o.x = fmaxf(o.x, 0.f); o.y = fmaxf(o.y, 0.f);
                    o.z = fmaxf(o.z, 0.f); o.w = fmaxf(o.w, 0.f);
                }
                *(float4*)&out[((size_t)(b*onch + coff + cc))*HW + (size_t)oy*WW + ox] = o;
            }
        }
    }
}

// ---------------- conv2: 1x1 32->1 + BN + ReLU ---------------------------
__global__ __launch_bounds__(256) void conv2_kernel(
    const float* __restrict__ w2, const float* __restrict__ bg,
    const float* __restrict__ bb, const float* __restrict__ bm,
    const float* __restrict__ bv)
{
    __shared__ float sw[32];
    if (threadIdx.x < 32) sw[threadIdx.x] = w2[threadIdx.x];
    __syncthreads();
    int gid = blockIdx.x*256 + threadIdx.x;
    int b   = gid / (HW/4);
    int r4  = (gid - b*(HW/4))*4;
    const float* xb = g_x1 + (size_t)b*32*HW + r4;
    float4 acc = make_float4(0.f,0.f,0.f,0.f);
#pragma unroll 8
    for (int c = 0; c < 32; c++) {
        float4 vv = *(const float4*)(xb + (size_t)c*HW);
        float wv = sw[c];
        acc.x = fmaf(vv.x, wv, acc.x);
        acc.y = fmaf(vv.y, wv, acc.y);
        acc.z = fmaf(vv.z, wv, acc.z);
        acc.w = fmaf(vv.w, wv, acc.w);
    }
    float s    = bg[0]*rsqrtf(bv[0]+EPSV);
    float bias = bb[0] - bm[0]*s;
    float4 o;
    o.x = fmaxf(fmaf(acc.x, s, bias), 0.f);
    o.y = fmaxf(fmaf(acc.y, s, bias), 0.f);
    o.z = fmaxf(fmaf(acc.z, s, bias), 0.f);
    o.w = fmaxf(fmaf(acc.w, s, bias), 0.f);
    *(float4*)&g_cspn[(size_t)b*HW + r4] = o;
}

// ---------------- CSPN: 9-tap weighted sum -------------------------------
__global__ __launch_bounds__(256) void cspn_kernel()
{
    int gid = blockIdx.x*256 + threadIdx.x;
    int b   = gid / HW;
    int r   = gid - b*HW;
    int y   = r >> 8, x = r & 255;
    const float* cs = g_cspn + (size_t)b*HW;
    const float* k  = g_gk2 + (size_t)b*9*HW + r;
    float acc = 0.f;
#pragma unroll
    for (int j = 0; j < 9; j++) {
        int yy = y + j/3 - 1, xx = x + j%3 - 1;
        float pv = ((unsigned)yy < 256u && (unsigned)xx < 256u) ? cs[yy*WW+xx] : 0.f;
        acc = fmaf(pv, k[(size_t)j*HW], acc);
    }
    g_cat[(size_t)b*32*HW + r] = acc;   // channel 0
}

// ---------------- bilinear upsample 2x (align-corners style) -------------
__global__ __launch_bounds__(256) void upsample_kernel(float* __restrict__ out)
{
    int gid = blockIdx.x*256 + threadIdx.x;
    int xo  = (gid & 127) << 2;
    int t   = gid >> 7;
    int yo  = t & 511;
    int bc  = t >> 9;                          // b*32 + c
    const float* src = g_cat + (size_t)bc*HW;
    const float scale = 255.f/511.f;
    float ysf = yo * scale;
    int y0 = (int)ysf;
    float wy = ysf - (float)y0;
    int y1 = min(y0+1, 255);
    const float* r0 = src + y0*WW;
    const float* r1 = src + y1*WW;
    float res[4];
#pragma unroll
    for (int i = 0; i < 4; i++) {
        float xsf = (xo+i) * scale;
        int x0 = (int)xsf;
        float wx = xsf - (float)x0;
        int x1 = min(x0+1, 255);
        float top = r0[x0]*(1.f-wx) + r0[x1]*wx;
        float bot = r1[x0]*(1.f-wx) + r1[x1]*wx;
        res[i] = top*(1.f-wy) + bot*wy;
    }
    *(float4*)&out[((size_t)bc*512 + yo)*512 + xo] =
        make_float4(res[0], res[1], res[2], res[3]);
}

// --------------------------------------------------------------------------
extern "C" void kernel_launch(void* const* d_in, const int* in_sizes, int n_in,
                              void* d_out, int out_size)
{
    const float* x     = (const float*)d_in[0];
    const float* guide = (const float*)d_in[1];
    const float* depth = (const float*)d_in[2];
    const float* c1w   = (const float*)d_in[3];
    const float* b1g = (const float*)d_in[4],  *b1b = (const float*)d_in[5];
    const float* b1m = (const float*)d_in[6],  *b1v = (const float*)d_in[7];
    const float* c2w   = (const float*)d_in[8];
    const float* b2g = (const float*)d_in[9],  *b2b = (const float*)d_in[10];
    const float* b2m = (const float*)d_in[11], *b2v = (const float*)d_in[12];
    const float* c3w   = (const float*)d_in[13];
    const float* b3g = (const float*)d_in[14], *b3b = (const float*)d_in[15];
    const float* b3m = (const float*)d_in[16], *b3v = (const float*)d_in[17];
    const float* gw    = (const float*)d_in[18];
    const float* bgg = (const float*)d_in[19], *bgb = (const float*)d_in[20];
    const float* bgm = (const float*)d_in[21], *bgv = (const float*)d_in[22];
    const float* enc   = (const float*)d_in[23];

    float *px1, *pcat, *pgk, *pgk2;
    cudaGetSymbolAddress((void**)&px1,  g_x1);
    cudaGetSymbolAddress((void**)&pcat, g_cat);
    cudaGetSymbolAddress((void**)&pgk,  g_gk);
    cudaGetSymbolAddress((void**)&pgk2, g_gk2);

    dim3 gridA(WW/32, HH/8, BATCH);

    // 1) fused add + conv1 5x5 + BN + ReLU -> g_x1
    conv1_kernel<<<gridA, 256>>>(x, guide, depth, c1w, b1g, b1b, b1m, b1v);

    // 2) conv3 3x3 32->31 + BN + ReLU -> g_cat channels 1..31
    conv3x3_kernel<32,4,8,true,true,false><<<gridA, 256>>>(
        px1, c3w, b3g, b3b, b3m, b3v, pcat, 31, 32, 1);

    // 3) gen 3x3 32->8 + BN + normalize + concat(g_mid) -> g_gk (9 ch)
    dim3 gridG(WW/32, HH/16, BATCH);
    conv3x3_kernel<32,1,16,true,false,true><<<gridG, 128>>>(
        px1, gw, bgg, bgb, bgm, bgv, pgk, 8, 9, 0);

    // 4) conv2 1x1 32->1 + BN + ReLU -> g_cspn
    conv2_kernel<<<BATCH*HW/1024, 256>>>(c2w, b2g, b2b, b2m, b2v);

    // 5) encoder conv 9->9 3x3 (no BN) -> g_gk2
    conv3x3_kernel<9,2,8,false,false,false><<<gridA, 128>>>(
        pgk, enc, nullptr, nullptr, nullptr, nullptr, pgk2, 9, 9, 0);

    // 6) CSPN weighted sum -> g_cat channel 0
    cspn_kernel<<<BATCH*HW/256, 256>>>();

    // 7) bilinear upsample 2x -> d_out
    upsample_kernel<<<(BATCH*32*512*512)/1024, 256>>>((float*)d_out);
}

// round 8
// speedup vs baseline: 1.3402x; 1.2703x over previous
#include <cuda_runtime.h>
#include <cuda_bf16.h>
#include <cstdint>

#define BATCH 8
#define CH    32
#define HH    256
#define WW    256
#define HW    (HH*WW)
#define EPSV  1e-5f

typedef unsigned long long ull;

// ---------------- packed f32x2 helpers (used by 3x3 convs) ----------------
__device__ __forceinline__ ull pk2(float lo, float hi) {
    ull r;
    asm("mov.b64 %0, {%1, %2};" : "=l"(r)
        : "r"(__float_as_uint(lo)), "r"(__float_as_uint(hi)));
    return r;
}
__device__ __forceinline__ void fma2(ull& d, ull a, ull b) {
    asm("fma.rn.f32x2 %0, %1, %2, %3;" : "=l"(d) : "l"(a), "l"(b), "l"(d));
}
__device__ __forceinline__ float2 upk(ull v) {
    unsigned lo, hi;
    asm("mov.b64 {%0, %1}, %2;" : "=r"(lo), "=r"(hi) : "l"(v));
    return make_float2(__uint_as_float(lo), __uint_as_float(hi));
}

// ---------------- HMMA m16n8k16 bf16 (base sm_103-legal) -------------------
__device__ __forceinline__ void hmma(float& d0, float& d1, float& d2, float& d3,
                                     uint32_t a0, uint32_t a1, uint32_t a2, uint32_t a3,
                                     uint32_t b0, uint32_t b1) {
    asm volatile("mma.sync.aligned.m16n8k16.row.col.f32.bf16.bf16.f32 "
                 "{%0,%1,%2,%3}, {%4,%5,%6,%7}, {%8,%9}, {%0,%1,%2,%3};"
                 : "+f"(d0), "+f"(d1), "+f"(d2), "+f"(d3)
                 : "r"(a0), "r"(a1), "r"(a2), "r"(a3), "r"(b0), "r"(b1));
}

__device__ __forceinline__ uint32_t pkbf(float lo, float hi) {
    __nv_bfloat16 h0 = __float2bfloat16(lo);
    __nv_bfloat16 h1 = __float2bfloat16(hi);
    return (uint32_t)__bfloat16_as_ushort(h0) |
           ((uint32_t)__bfloat16_as_ushort(h1) << 16);
}

// ---------------- scratch (device globals; no allocation) ------------------
__device__ float g_x1[(size_t)BATCH*CH*HW];    // conv1 output            (64 MB)
__device__ float g_cat[(size_t)BATCH*CH*HW];   // ch0=guided, ch1..31=x3  (64 MB)
__device__ float g_cspn[(size_t)BATCH*HW];     // conv2 output            ( 2 MB)
__device__ float g_gk[(size_t)BATCH*9*HW];     // guide kernel (9ch)      (18 MB)
__device__ float g_gk2[(size_t)BATCH*9*HW];    // encoder(guide kernel)   (18 MB)
__device__ uint32_t g_wb1[25600];              // conv1 B frags (100 KB)

// ---------------- conv1 weight prep: B-fragment lane order ------------------
// layout: [tap 25][pass 2 (wh/wl)][ck 2][nb 4][rg 2][lane 32] of bf16x2
__global__ __launch_bounds__(256) void prep_b1_kernel(const float* __restrict__ w)
{
    int i = blockIdx.x*256 + threadIdx.x;
    if (i >= 25600) return;
    int lane = i & 31;
    int r2 = i >> 5;
    int rg = r2 & 1;  r2 >>= 1;
    int nb = r2 & 3;  r2 >>= 2;
    int ck = r2 & 1;  r2 >>= 1;
    int ps = r2 & 1;  r2 >>= 1;
    int t  = r2;                        // 0..24
    int n   = nb*8 + (lane >> 2);       // cout
    int cin = ck*16 + (lane & 3)*2 + rg*8;
    float w0 = w[n*800 + cin*25 + t];
    float w1 = w[n*800 + (cin+1)*25 + t];
    uint32_t out;
    if (ps == 0) out = pkbf(w0, w1);
    else {
        float h0 = __bfloat162float(__float2bfloat16(w0));
        float h1 = __bfloat162float(__float2bfloat16(w1));
        out = pkbf(w0 - h0, w1 - h1);
    }
    g_wb1[i] = out;
}

// ---------------- conv1 via HMMA: split-bf16 implicit GEMM -----------------
// CTA 256 thr, tile 32x8 px, warp w = row w; 2 m16 tiles/warp, N=32 couts.
// dyn smem: [0..102400)  B frags (uint32, copy of g_wb1)
//           [102400..136960)  xh plane: 12 rows x 36 cols x 80B (cin*2 inside)
//           [136960..171520)  xl plane (same layout)
//           [171520..171776)  bn scale[32] + bias[32]
#define C1_WB_OFF 0
#define C1_XH_OFF 102400
#define C1_XL_OFF 136960
#define C1_BN_OFF 171520
#define C1_SMEM   171776

__global__ __launch_bounds__(256, 1) void conv1_mma_kernel(
    const float* __restrict__ x,  const float* __restrict__ gu,
    const float* __restrict__ dp,
    const float* __restrict__ bg, const float* __restrict__ bb,
    const float* __restrict__ bm, const float* __restrict__ bv)
{
    extern __shared__ __align__(16) unsigned char smem[];
    uint32_t* s_wb    = reinterpret_cast<uint32_t*>(smem + C1_WB_OFF);
    float*    s_scale = reinterpret_cast<float*>(smem + C1_BN_OFF);
    float*    s_bias  = reinterpret_cast<float*>(smem + C1_BN_OFF + 128);

    const int tid  = threadIdx.x;
    const int w    = tid >> 5;           // warp = image row 0..7
    const int lane = tid & 31;
    const int bx0  = blockIdx.x << 5;
    const int by0  = blockIdx.y << 3;
    const int b    = blockIdx.z;

    // ---- copy B fragments (100 KB) ----
    {
        const uint4* src = reinterpret_cast<const uint4*>(g_wb1);
        uint4* dst = reinterpret_cast<uint4*>(s_wb);
#pragma unroll
        for (int t = 0; t < 25; t++) dst[t*256 + tid] = src[t*256 + tid];
    }
    if (tid < 32) {
        float s = bg[tid] * rsqrtf(bv[tid] + EPSV);
        s_scale[tid] = s;
        s_bias[tid]  = bb[tid] - bm[tid]*s;
    }

    // ---- stage input as bf16 hi/lo planes: off = (r*36+c)*80 + cin*2 ----
    for (int i = tid; i < 32*12*36; i += 256) {
        int cin = i / 432;
        int rem = i - cin*432;
        int r = rem / 36, c = rem - r*36;
        int gy = by0 - 2 + r, gx = bx0 - 2 + c;
        float v = 0.f;
        if ((unsigned)gy < 256u && (unsigned)gx < 256u) {
            size_t idx = ((size_t)(b*32 + cin))*HW + (size_t)gy*WW + gx;
            v = x[idx] + gu[idx] + dp[idx];
        }
        __nv_bfloat16 h = __float2bfloat16(v);
        uint32_t off = (uint32_t)(r*36 + c)*80u + (uint32_t)cin*2u;
        *reinterpret_cast<__nv_bfloat16*>(smem + C1_XH_OFF + off) = h;
        *reinterpret_cast<__nv_bfloat16*>(smem + C1_XL_OFF + off) =
            __float2bfloat16(v - __bfloat162float(h));
    }
    __syncthreads();

    float acc[2][4][4];
#pragma unroll
    for (int mt = 0; mt < 2; mt++)
#pragma unroll
        for (int nb = 0; nb < 4; nb++)
#pragma unroll
            for (int q = 0; q < 4; q++) acc[mt][nb][q] = 0.f;

    const int pix = lane >> 2;               // 0..7
    const uint32_t cq = (uint32_t)(lane & 3) * 4u;  // byte offset of cin pair

#pragma unroll 1
    for (int t = 0; t < 25; t++) {
        const int ky = t / 5, kx = t - ky*5;
        const uint32_t* wb = s_wb + t*1024;

        // B regs: [ps][ck][nb][rg]
        uint32_t B[2][2][4][2];
#pragma unroll
        for (int ps = 0; ps < 2; ps++)
#pragma unroll
            for (int ck = 0; ck < 2; ck++)
#pragma unroll
                for (int nb = 0; nb < 4; nb++) {
                    B[ps][ck][nb][0] = wb[(((ps*2+ck)*4+nb)*2+0)*32 + lane];
                    B[ps][ck][nb][1] = wb[(((ps*2+ck)*4+nb)*2+1)*32 + lane];
                }

        const uint32_t rowoff = (uint32_t)(w + ky)*2880u;
#pragma unroll
        for (int mt = 0; mt < 2; mt++) {
            const uint32_t base =
                rowoff + (uint32_t)(mt*16 + pix + kx)*80u + cq;
            const unsigned char* ah = smem + C1_XH_OFF + base;
            const unsigned char* al = smem + C1_XL_OFF + base;
            // xh chunk0 (cin 0..15), chunk1 (cin 16..31)
            uint32_t h00 = *(const uint32_t*)(ah);
            uint32_t h01 = *(const uint32_t*)(ah + 640);
            uint32_t h02 = *(const uint32_t*)(ah + 16);
            uint32_t h03 = *(const uint32_t*)(ah + 656);
            uint32_t h10 = *(const uint32_t*)(ah + 32);
            uint32_t h11 = *(const uint32_t*)(ah + 672);
            uint32_t h12 = *(const uint32_t*)(ah + 48);
            uint32_t h13 = *(const uint32_t*)(ah + 688);
            uint32_t l00 = *(const uint32_t*)(al);
            uint32_t l01 = *(const uint32_t*)(al + 640);
            uint32_t l02 = *(const uint32_t*)(al + 16);
            uint32_t l03 = *(const uint32_t*)(al + 656);
            uint32_t l10 = *(const uint32_t*)(al + 32);
            uint32_t l11 = *(const uint32_t*)(al + 672);
            uint32_t l12 = *(const uint32_t*)(al + 48);
            uint32_t l13 = *(const uint32_t*)(al + 688);
#pragma unroll
            for (int nb = 0; nb < 4; nb++) {
                float* d = acc[mt][nb];
                hmma(d[0],d[1],d[2],d[3], h00,h01,h02,h03,
                     B[0][0][nb][0], B[0][0][nb][1]);   // xh * wh  k0-15
                hmma(d[0],d[1],d[2],d[3], h10,h11,h12,h13,
                     B[0][1][nb][0], B[0][1][nb][1]);   // xh * wh  k16-31
                hmma(d[0],d[1],d[2],d[3], l00,l01,l02,l03,
                     B[0][0][nb][0], B[0][0][nb][1]);   // xl * wh  k0-15
                hmma(d[0],d[1],d[2],d[3], l10,l11,l12,l13,
                     B[0][1][nb][0], B[0][1][nb][1]);   // xl * wh  k16-31
                hmma(d[0],d[1],d[2],d[3], h00,h01,h02,h03,
                     B[1][0][nb][0], B[1][0][nb][1]);   // xh * wl  k0-15
                hmma(d[0],d[1],d[2],d[3], h10,h11,h12,h13,
                     B[1][1][nb][0], B[1][1][nb][1]);   // xh * wl  k16-31
            }
        }
    }

    // ---- epilogue: BN + ReLU + store ----
    const int y = by0 + w;
    float* outb = g_x1 + (size_t)b*32*HW + (size_t)y*WW;
#pragma unroll
    for (int nb = 0; nb < 4; nb++) {
        int c0 = nb*8 + (lane & 3)*2;
        float s0 = s_scale[c0],   bi0 = s_bias[c0];
        float s1 = s_scale[c0+1], bi1 = s_bias[c0+1];
        float* p0 = outb + (size_t)c0*HW;
        float* p1 = outb + (size_t)(c0+1)*HW;
#pragma unroll
        for (int mt = 0; mt < 2; mt++) {
            int xp = bx0 + mt*16 + pix;
            float* d = acc[mt][nb];
            p0[xp]     = fmaxf(fmaf(d[0], s0, bi0), 0.f);
            p1[xp]     = fmaxf(fmaf(d[1], s1, bi1), 0.f);
            p0[xp + 8] = fmaxf(fmaf(d[2], s0, bi0), 0.f);
            p1[xp + 8] = fmaxf(fmaf(d[3], s1, bi1), 0.f);
        }
    }
}

// ---------------- generic 3x3 conv (pad 1), f32x2 packed -------------------
template<int CIN, int G, int TH, bool HASBN, bool RELU, bool GEN>
__global__ void conv3x3_kernel(
    const float* __restrict__ in, const float* __restrict__ w,
    const float* __restrict__ bg, const float* __restrict__ bb,
    const float* __restrict__ bm, const float* __restrict__ bv,
    float* __restrict__ out, int nco, int onch, int coff)
{
    constexpr int NPIX = 8*TH;
    constexpr int NT   = NPIX*G;
    constexpr int NCOP = G*8;
    constexpr int IN_ELEMS = (TH+2)*34;
    constexpr int IN_IT = (IN_ELEMS + NT - 1) / NT;
    constexpr int W_ELEMS = NCOP*9;
    constexpr int W_IT = (W_ELEMS + NT - 1) / NT;

    __shared__ float s_in[2][(TH+2)*40];
    __shared__ ull   s_w2[2][NCOP*9];
    const int tid = threadIdx.x;
    const int cg  = tid / NPIX;
    const int p   = tid % NPIX;
    const int px  = (p & 7) << 2;
    const int py  = p >> 3;
    const int bx0 = blockIdx.x << 5;
    const int by0 = blockIdx.y * TH;
    const int b   = blockIdx.z;

    ull acc01[8], acc23[8];
#pragma unroll
    for (int c = 0; c < 8; c++) { acc01[c] = 0ULL; acc23[c] = 0ULL; }

    float rin[IN_IT];
    float rw[W_IT];

    auto fetch = [&](int cin) {
        const float* ib = in + ((size_t)(b*CIN + cin))*HW;
#pragma unroll
        for (int t = 0; t < IN_IT; t++) {
            int i = tid + t*NT;
            float v = 0.f;
            if (i < IN_ELEMS) {
                int r = i / 34, c2 = i - r*34;
                int gy = by0 - 1 + r, gx = bx0 - 1 + c2;
                if ((unsigned)gy < 256u && (unsigned)gx < 256u)
                    v = ib[gy*WW + gx];
            }
            rin[t] = v;
        }
#pragma unroll
        for (int t = 0; t < W_IT; t++) {
            int i = tid + t*NT;
            float v = 0.f;
            if (i < W_ELEMS) {
                int co = i / 9, q = i - co*9;
                if (co < nco) v = w[(co*CIN + cin)*9 + q];
            }
            rw[t] = v;
        }
    };
    auto commit = [&](int buf) {
#pragma unroll
        for (int t = 0; t < IN_IT; t++) {
            int i = tid + t*NT;
            if (i < IN_ELEMS) {
                int r = i / 34, c2 = i - r*34;
                s_in[buf][r*40 + c2] = rin[t];
            }
        }
#pragma unroll
        for (int t = 0; t < W_IT; t++) {
            int i = tid + t*NT;
            if (i < W_ELEMS) s_w2[buf][i] = pk2(rw[t], rw[t]);
        }
    };

    fetch(0); commit(0);

#pragma unroll 1
    for (int cin = 0; cin < CIN; cin++) {
        __syncthreads();
        if (cin + 1 < CIN) fetch(cin + 1);
        const int buf = cin & 1;
#pragma unroll
        for (int ky = 0; ky < 3; ky++) {
            const float* row = &s_in[buf][(py+ky)*40 + px];
            float4 a  = *(const float4*)row;
            float2 b2 = *(const float2*)(row + 4);
            ull pe0 = pk2(a.x, a.y), pe1 = pk2(a.z, a.w), pe2 = pk2(b2.x, b2.y);
            ull po0 = pk2(a.y, a.z), po1 = pk2(a.w, b2.x);
#pragma unroll
            for (int c = 0; c < 8; c++) {
                const ull* wr = &s_w2[buf][(cg*8+c)*9 + ky*3];
                ull w0 = wr[0], w1 = wr[1], w2 = wr[2];
                fma2(acc01[c], pe0, w0); fma2(acc23[c], pe1, w0);
                fma2(acc01[c], po0, w1); fma2(acc23[c], po1, w1);
                fma2(acc01[c], pe1, w2); fma2(acc23[c], pe2, w2);
            }
        }
        __syncthreads();
        if (cin + 1 < CIN) commit((cin + 1) & 1);
    }

    const int oy = by0 + py, ox = bx0 + px;
    if (GEN) {
        float v[8][4];
#pragma unroll
        for (int c = 0; c < 8; c++) {
            float s = 1.f, bias = 0.f;
            if (HASBN) { s = bg[c]*rsqrtf(bv[c]+EPSV); bias = bb[c]-bm[c]*s; }
            float2 v01 = upk(acc01[c]), v23 = upk(acc23[c]);
            v[c][0] = fmaf(v01.x, s, bias);
            v[c][1] = fmaf(v01.y, s, bias);
            v[c][2] = fmaf(v23.x, s, bias);
            v[c][3] = fmaf(v23.y, s, bias);
        }
        float gk[9][4];
#pragma unroll
        for (int i = 0; i < 4; i++) {
            float asum = 0.f;
#pragma unroll
            for (int c = 0; c < 8; c++) asum += fabsf(v[c][i]);
            float inv = 1.f / asum;
            float ssum = 0.f;
#pragma unroll
            for (int c = 0; c < 8; c++) {
                float t = v[c][i]*inv;
                ssum += t;
                gk[c < 4 ? c : c+1][i] = t;
            }
            gk[4][i] = 1.f - ssum;
        }
#pragma unroll
        for (int j = 0; j < 9; j++) {
            float4 o = make_float4(gk[j][0], gk[j][1], gk[j][2], gk[j][3]);
            *(float4*)&out[((size_t)(b*onch + j))*HW + (size_t)oy*WW + ox] = o;
        }
    } else {
#pragma unroll
        for (int c = 0; c < 8; c++) {
            int cc = cg*8 + c;
            if (cc < nco) {
                float s = 1.f, bias = 0.f;
                if (HASBN) { s = bg[cc]*rsqrtf(bv[cc]+EPSV); bias = bb[cc]-bm[cc]*s; }
                float2 v01 = upk(acc01[c]), v23 = upk(acc23[c]);
                float4 o;
                o.x = fmaf(v01.x, s, bias);
                o.y = fmaf(v01.y, s, bias);
                o.z = fmaf(v23.x, s, bias);
                o.w = fmaf(v23.y, s, bias);
                if (RELU) {
                    o.x = fmaxf(o.x, 0.f); o.y = fmaxf(o.y, 0.f);
                    o.z = fmaxf(o.z, 0.f); o.w = fmaxf(o.w, 0.f);
                }
                *(float4*)&out[((size_t)(b*onch + coff + cc))*HW + (size_t)oy*WW + ox] = o;
            }
        }
    }
}

// ---------------- conv2: 1x1 32->1 + BN + ReLU -----------------------------
__global__ __launch_bounds__(256) void conv2_kernel(
    const float* __restrict__ w2, const float* __restrict__ bg,
    const float* __restrict__ bb, const float* __restrict__ bm,
    const float* __restrict__ bv)
{
    __shared__ float sw[32];
    if (threadIdx.x < 32) sw[threadIdx.x] = w2[threadIdx.x];
    __syncthreads();
    int gid = blockIdx.x*256 + threadIdx.x;
    int b   = gid / (HW/4);
    int r4  = (gid - b*(HW/4))*4;
    const float* xb = g_x1 + (size_t)b*32*HW + r4;
    float4 acc = make_float4(0.f,0.f,0.f,0.f);
#pragma unroll 8
    for (int c = 0; c < 32; c++) {
        float4 vv = *(const float4*)(xb + (size_t)c*HW);
        float wv = sw[c];
        acc.x = fmaf(vv.x, wv, acc.x);
        acc.y = fmaf(vv.y, wv, acc.y);
        acc.z = fmaf(vv.z, wv, acc.z);
        acc.w = fmaf(vv.w, wv, acc.w);
    }
    float s    = bg[0]*rsqrtf(bv[0]+EPSV);
    float bias = bb[0] - bm[0]*s;
    float4 o;
    o.x = fmaxf(fmaf(acc.x, s, bias), 0.f);
    o.y = fmaxf(fmaf(acc.y, s, bias), 0.f);
    o.z = fmaxf(fmaf(acc.z, s, bias), 0.f);
    o.w = fmaxf(fmaf(acc.w, s, bias), 0.f);
    *(float4*)&g_cspn[(size_t)b*HW + r4] = o;
}

// ---------------- CSPN: 9-tap weighted sum ---------------------------------
__global__ __launch_bounds__(256) void cspn_kernel()
{
    int gid = blockIdx.x*256 + threadIdx.x;
    int b   = gid / HW;
    int r   = gid - b*HW;
    int y   = r >> 8, x = r & 255;
    const float* cs = g_cspn + (size_t)b*HW;
    const float* k  = g_gk2 + (size_t)b*9*HW + r;
    float acc = 0.f;
#pragma unroll
    for (int j = 0; j < 9; j++) {
        int yy = y + j/3 - 1, xx = x + j%3 - 1;
        float pv = ((unsigned)yy < 256u && (unsigned)xx < 256u) ? cs[yy*WW+xx] : 0.f;
        acc = fmaf(pv, k[(size_t)j*HW], acc);
    }
    g_cat[(size_t)b*32*HW + r] = acc;   // channel 0
}

// ---------------- bilinear upsample 2x --------------------------------------
__global__ __launch_bounds__(256) void upsample_kernel(float* __restrict__ out)
{
    int gid = blockIdx.x*256 + threadIdx.x;
    int xo  = (gid & 127) << 2;
    int t   = gid >> 7;
    int yo  = t & 511;
    int bc  = t >> 9;                          // b*32 + c
    const float* src = g_cat + (size_t)bc*HW;
    const float scale = 255.f/511.f;
    float ysf = yo * scale;
    int y0 = (int)ysf;
    float wy = ysf - (float)y0;
    int y1 = min(y0+1, 255);
    const float* r0 = src + y0*WW;
    const float* r1 = src + y1*WW;
    float res[4];
#pragma unroll
    for (int i = 0; i < 4; i++) {
        float xsf = (xo+i) * scale;
        int x0 = (int)xsf;
        float wx = xsf - (float)x0;
        int x1 = min(x0+1, 255);
        float top = r0[x0]*(1.f-wx) + r0[x1]*wx;
        float bot = r1[x0]*(1.f-wx) + r1[x1]*wx;
        res[i] = top*(1.f-wy) + bot*wy;
    }
    *(float4*)&out[((size_t)bc*512 + yo)*512 + xo] =
        make_float4(res[0], res[1], res[2], res[3]);
}

// ----------------------------------------------------------------------------
extern "C" void kernel_launch(void* const* d_in, const int* in_sizes, int n_in,
                              void* d_out, int out_size)
{
    const float* x     = (const float*)d_in[0];
    const float* guide = (const float*)d_in[1];
    const float* depth = (const float*)d_in[2];
    const float* c1w   = (const float*)d_in[3];
    const float* b1g = (const float*)d_in[4],  *b1b = (const float*)d_in[5];
    const float* b1m = (const float*)d_in[6],  *b1v = (const float*)d_in[7];
    const float* c2w   = (const float*)d_in[8];
    const float* b2g = (const float*)d_in[9],  *b2b = (const float*)d_in[10];
    const float* b2m = (const float*)d_in[11], *b2v = (const float*)d_in[12];
    const float* c3w   = (const float*)d_in[13];
    const float* b3g = (const float*)d_in[14], *b3b = (const float*)d_in[15];
    const float* b3m = (const float*)d_in[16], *b3v = (const float*)d_in[17];
    const float* gw    = (const float*)d_in[18];
    const float* bgg = (const float*)d_in[19], *bgb = (const float*)d_in[20];
    const float* bgm = (const float*)d_in[21], *bgv = (const float*)d_in[22];
    const float* enc   = (const float*)d_in[23];

    float *px1, *pcat, *pgk, *pgk2;
    cudaGetSymbolAddress((void**)&px1,  g_x1);
    cudaGetSymbolAddress((void**)&pcat, g_cat);
    cudaGetSymbolAddress((void**)&pgk,  g_gk);
    cudaGetSymbolAddress((void**)&pgk2, g_gk2);

    cudaFuncSetAttribute(conv1_mma_kernel,
                         cudaFuncAttributeMaxDynamicSharedMemorySize, C1_SMEM);

    // 0) prep conv1 weights into B-fragment lane order (bf16 wh/wl)
    prep_b1_kernel<<<100, 256>>>(c1w);

    // 1) fused add + conv1 5x5 + BN + ReLU via HMMA -> g_x1
    dim3 gridC1(WW/32, HH/8, BATCH);
    conv1_mma_kernel<<<gridC1, 256, C1_SMEM>>>(x, guide, depth,
                                               b1g, b1b, b1m, b1v);

    dim3 gridA(WW/32, HH/8, BATCH);

    // 2) conv3 3x3 32->31 + BN + ReLU -> g_cat channels 1..31
    conv3x3_kernel<32,4,8,true,true,false><<<gridA, 256>>>(
        px1, c3w, b3g, b3b, b3m, b3v, pcat, 31, 32, 1);

    // 3) gen 3x3 32->8 + BN + normalize + concat(g_mid) -> g_gk (9 ch)
    dim3 gridG(WW/32, HH/16, BATCH);
    conv3x3_kernel<32,1,16,true,false,true><<<gridG, 128>>>(
        px1, gw, bgg, bgb, bgm, bgv, pgk, 8, 9, 0);

    // 4) conv2 1x1 32->1 + BN + ReLU -> g_cspn
    conv2_kernel<<<BATCH*HW/1024, 256>>>(c2w, b2g, b2b, b2m, b2v);

    // 5) encoder conv 9->9 3x3 (no BN) -> g_gk2
    conv3x3_kernel<9,2,8,false,false,false><<<gridA, 128>>>(
        pgk, enc, nullptr, nullptr, nullptr, nullptr, pgk2, 9, 9, 0);

    // 6) CSPN weighted sum -> g_cat channel 0
    cspn_kernel<<<BATCH*HW/256, 256>>>();

    // 7) bilinear upsample 2x -> d_out
    upsample_kernel<<<(BATCH*32*512*512)/1024, 256>>>((float*)d_out);
}